// round 3
// baseline (speedup 1.0000x reference)
#include <cuda_runtime.h>
#include <math.h>

// ---------------------------------------------------------------------------
// Problem constants
// ---------------------------------------------------------------------------
#define BATCH    128
#define LATENT   256
#define HIDDEN   512
#define MNODES   64
#define NPAIRS   2016           // 64*63/2
#define G3       (3*HIDDEN)     // 1536

// ---------------------------------------------------------------------------
// Device scratch (no cudaMalloc allowed)
// ---------------------------------------------------------------------------
__device__ float g_Cm  [MNODES * LATENT];          // C[t][l]
__device__ float g_zWT [LATENT * BATCH];           // zW^T [l][b]
__device__ float g_AT  [G3 * BATCH];               // A^T  [g][b]
__device__ float g_D   [MNODES * G3];              // D    [t][g]
__device__ float g_P   [HIDDEN * HIDDEN];          // adj_W1a @ node_W
__device__ float g_Q   [HIDDEN * HIDDEN];          // adj_W1b @ node_W
__device__ float g_gh  [G3 * BATCH];               // recurrent GEMM out [g][b]
__device__ float g_h1T [MNODES * HIDDEN * BATCH];  // layer-0 hidden [t][k][b]
__device__ float g_h2T [MNODES * HIDDEN * BATCH];  // layer-1 hidden [t][k][b]
__device__ float g_gi1 [MNODES * G3 * BATCH];      // layer-1 input proj [t][g][b]
__device__ float g_U   [BATCH * MNODES * HIDDEN];  // [b][t][h]
__device__ float g_V   [BATCH * MNODES * HIDDEN];  // [b][t][h] (+adj_b1)
__device__ int   g_ii  [NPAIRS];
__device__ int   g_jj  [NPAIRS];

// ---------------------------------------------------------------------------
// Generic tiled fp32 GEMM:  C[m][n] = sum_k A(m,k) * B(n,k)  (+ bias[n])
//  A_ROW : A stored row-major (M x K, lda) else K-major (K x M, lda)
//  B_NK  : B stored (N x K, ldb) else (K x N, ldb)
//  C row-major with ldc. blockIdx.z batching via aZ/bZ/cZ element strides.
// ---------------------------------------------------------------------------
template<int BM, int BN, int BK, int TM, int TN, bool A_ROW, bool B_NK>
__global__ void sgemm_k(const float* __restrict__ Ag, const float* __restrict__ Bg,
                        float* __restrict__ Cg, const float* __restrict__ bias,
                        int K, int lda, int ldb, int ldc,
                        long aZ, long bZ, long cZ)
{
    const float* A = Ag + (long)blockIdx.z * aZ;
    const float* B = Bg + (long)blockIdx.z * bZ;
    float*       C = Cg + (long)blockIdx.z * cZ;

    __shared__ float As[BK][BM];
    __shared__ float Bs[BK][BN];

    constexpr int NTH = (BM / TM) * (BN / TN);
    const int tid  = threadIdx.x;
    const int tcol = tid % (BN / TN);
    const int trow = tid / (BN / TN);
    const int m0   = blockIdx.y * BM;
    const int n0   = blockIdx.x * BN;

    float acc[TM][TN];
#pragma unroll
    for (int i = 0; i < TM; i++)
#pragma unroll
        for (int j = 0; j < TN; j++) acc[i][j] = 0.f;

    for (int k0 = 0; k0 < K; k0 += BK) {
#pragma unroll
        for (int idx = tid; idx < BM * BK; idx += NTH) {
            int m = idx / BK, kk = idx % BK;
            As[kk][m] = A_ROW ? A[(long)(m0 + m) * lda + (k0 + kk)]
                              : A[(long)(k0 + kk) * lda + (m0 + m)];
        }
#pragma unroll
        for (int idx = tid; idx < BK * BN; idx += NTH) {
            int kk = idx / BN, n = idx % BN;
            Bs[kk][n] = B_NK ? B[(long)(n0 + n) * ldb + (k0 + kk)]
                             : B[(long)(k0 + kk) * ldb + (n0 + n)];
        }
        __syncthreads();
#pragma unroll
        for (int kk = 0; kk < BK; kk++) {
            float a[TM], b[TN];
#pragma unroll
            for (int i = 0; i < TM; i++) a[i] = As[kk][trow * TM + i];
#pragma unroll
            for (int j = 0; j < TN; j++) b[j] = Bs[kk][tcol * TN + j];
#pragma unroll
            for (int i = 0; i < TM; i++)
#pragma unroll
                for (int j = 0; j < TN; j++)
                    acc[i][j] = fmaf(a[i], b[j], acc[i][j]);
        }
        __syncthreads();
    }

#pragma unroll
    for (int i = 0; i < TM; i++) {
        int m = m0 + trow * TM + i;
#pragma unroll
        for (int j = 0; j < TN; j++) {
            int n = n0 + tcol * TN + j;
            float v = acc[i][j];
            if (bias) v += bias[n];
            C[(long)m * ldc + n] = v;
        }
    }
}

// ---------------------------------------------------------------------------
// Small precompute kernels
// ---------------------------------------------------------------------------
__global__ void precompC_k(const float* __restrict__ pe, const float* __restrict__ emb,
                           const float* __restrict__ W_pre, const float* __restrict__ b_pre)
{
    int t = blockIdx.x, l = threadIdx.x;
    const float* w = W_pre + l * 512;
    float acc = b_pre[l];
    for (int d = 0; d < 256; d++)
        acc += pe[t * 256 + d] * w[d] + emb[t * 256 + d] * w[256 + d];
    g_Cm[t * 256 + l] = acc;
}

__global__ void precompzW_k(const float* __restrict__ z, const float* __restrict__ W_pre)
{
    int b = blockIdx.x, l = threadIdx.x;
    const float* w = W_pre + l * 512;
    float acc = 0.f;
    for (int d = 0; d < 256; d++)
        acc += z[b * 256 + d] * w[d];
    g_zWT[l * BATCH + b] = acc;
}

__global__ void pairidx_k()
{
    int p = blockIdx.x * blockDim.x + threadIdx.x;
    if (p >= NPAIRS) return;
    int i = 0, rem = p;
    while (rem >= 63 - i) { rem -= 63 - i; i++; }
    g_ii[p] = i;
    g_jj[p] = i + 1 + rem;
}

__global__ void zero_k(float* p, int n)
{
    int i = blockIdx.x * blockDim.x + threadIdx.x;
    if (i < n) p[i] = 0.f;
}

// ---------------------------------------------------------------------------
// GRU gate kernels. gh (no bias) laid out [g][b]; hidden seq [t][k][b].
// ---------------------------------------------------------------------------
__device__ __forceinline__ float sigm(float x) { return 1.f / (1.f + expf(-x)); }

__global__ void gate0_k(const float* __restrict__ bih, const float* __restrict__ bhh,
                        const int* __restrict__ n_nodes, int t, int first)
{
    int idx = blockIdx.x * blockDim.x + threadIdx.x;   // 65536
    int b = idx & (BATCH - 1);
    int j = idx >> 7;

    float ghr = 0.f, ghz = 0.f, ghn = 0.f, hprev = 0.f;
    if (!first) {
        ghr = g_gh[j * BATCH + b];
        ghz = g_gh[(HIDDEN + j) * BATCH + b];
        ghn = g_gh[(2 * HIDDEN + j) * BATCH + b];
        hprev = g_h1T[((long)(t - 1) * HIDDEN + j) * BATCH + b];
    }
    float gir = bih[j], giz = bih[HIDDEN + j], gin = bih[2 * HIDDEN + j];
    if (t < n_nodes[b]) {
        gir += g_AT[j * BATCH + b]                + g_D[t * G3 + j];
        giz += g_AT[(HIDDEN + j) * BATCH + b]     + g_D[t * G3 + HIDDEN + j];
        gin += g_AT[(2 * HIDDEN + j) * BATCH + b] + g_D[t * G3 + 2 * HIDDEN + j];
    }
    ghr += bhh[j]; ghz += bhh[HIDDEN + j]; ghn += bhh[2 * HIDDEN + j];

    float r  = sigm(gir + ghr);
    float zg = sigm(giz + ghz);
    float n  = tanhf(gin + r * ghn);
    float h  = (1.f - zg) * n + zg * hprev;
    g_h1T[((long)t * HIDDEN + j) * BATCH + b] = h;
}

__global__ void gate1_k(const float* __restrict__ bih, const float* __restrict__ bhh,
                        int t, int first)
{
    int idx = blockIdx.x * blockDim.x + threadIdx.x;
    int b = idx & (BATCH - 1);
    int j = idx >> 7;

    float ghr = 0.f, ghz = 0.f, ghn = 0.f, hprev = 0.f;
    if (!first) {
        ghr = g_gh[j * BATCH + b];
        ghz = g_gh[(HIDDEN + j) * BATCH + b];
        ghn = g_gh[(2 * HIDDEN + j) * BATCH + b];
        hprev = g_h2T[((long)(t - 1) * HIDDEN + j) * BATCH + b];
    }
    const float* gi = g_gi1 + (long)t * G3 * BATCH;
    float gir = gi[j * BATCH + b]                + bih[j];
    float giz = gi[(HIDDEN + j) * BATCH + b]     + bih[HIDDEN + j];
    float gin = gi[(2 * HIDDEN + j) * BATCH + b] + bih[2 * HIDDEN + j];
    ghr += bhh[j]; ghz += bhh[HIDDEN + j]; ghn += bhh[2 * HIDDEN + j];

    float r  = sigm(gir + ghr);
    float zg = sigm(giz + ghz);
    float n  = tanhf(gin + r * ghn);
    float h  = (1.f - zg) * n + zg * hprev;
    g_h2T[((long)t * HIDDEN + j) * BATCH + b] = h;
}

// ---------------------------------------------------------------------------
// Pair kernel: logits + Gumbel hard decision -> writes 1s into zeroed adj.
//   hmid = relu(U[b,i] + V[b,j])   (V already has adj_b1 folded in)
//   l0 = hmid . W2[0] + b2[0] ; l1 = hmid . W2[1] + b2[1]
//   adj[b,i,j] = adj[b,j,i] = (l0+g0 >= l1+g1)
// grid (128, 2), 256 threads (8 warps): warp per pair, strided.
// ---------------------------------------------------------------------------
__global__ void pair_k(const float* __restrict__ W2, const float* __restrict__ b2,
                       const float* __restrict__ gu, const int* __restrict__ n_nodes,
                       float* __restrict__ out)
{
    int b    = blockIdx.x;
    int warp = (int)(blockIdx.y * 8 + (threadIdx.x >> 5));
    int lane = threadIdx.x & 31;
    int nb   = n_nodes[b];
    float* ob = out + (long)b * (MNODES * MNODES);

    float4 w2a[4], w2b[4];
#pragma unroll
    for (int q = 0; q < 4; q++) {
        w2a[q] = *(const float4*)(W2 + 4 * lane + 128 * q);
        w2b[q] = *(const float4*)(W2 + HIDDEN + 4 * lane + 128 * q);
    }

    for (int p = warp; p < NPAIRS; p += 16) {
        int j = g_jj[p];
        if (j >= nb) continue;           // i<j, so j<nb implies i<nb
        int i = g_ii[p];
        const float* Ui = g_U + ((long)b * MNODES + i) * HIDDEN;
        const float* Vj = g_V + ((long)b * MNODES + j) * HIDDEN;
        float a0 = 0.f, a1 = 0.f;
#pragma unroll
        for (int q = 0; q < 4; q++) {
            float4 u = *(const float4*)(Ui + 4 * lane + 128 * q);
            float4 v = *(const float4*)(Vj + 4 * lane + 128 * q);
            float m;
            m = fmaxf(u.x + v.x, 0.f); a0 = fmaf(m, w2a[q].x, a0); a1 = fmaf(m, w2b[q].x, a1);
            m = fmaxf(u.y + v.y, 0.f); a0 = fmaf(m, w2a[q].y, a0); a1 = fmaf(m, w2b[q].y, a1);
            m = fmaxf(u.z + v.z, 0.f); a0 = fmaf(m, w2a[q].z, a0); a1 = fmaf(m, w2b[q].z, a1);
            m = fmaxf(u.w + v.w, 0.f); a0 = fmaf(m, w2a[q].w, a0); a1 = fmaf(m, w2b[q].w, a1);
        }
#pragma unroll
        for (int s = 16; s > 0; s >>= 1) {
            a0 += __shfl_xor_sync(0xffffffffu, a0, s);
            a1 += __shfl_xor_sync(0xffffffffu, a1, s);
        }
        if (lane == 0) {
            float l0 = a0 + b2[0];
            float l1 = a1 + b2[1];
            const float* g = gu + ((long)b * NPAIRS + p) * 2;
            float g0 = -logf(-logf(g[0] + 1e-10f) + 1e-10f);
            float g1 = -logf(-logf(g[1] + 1e-10f) + 1e-10f);
            if (l0 + g0 >= l1 + g1) {
                ob[i * MNODES + j] = 1.f;
                ob[j * MNODES + i] = 1.f;
            }
        }
    }
}

// ---------------------------------------------------------------------------
// Host launch sequence (graph-capturable: kernel launches only)
// ---------------------------------------------------------------------------
extern "C" void kernel_launch(void* const* d_in, const int* in_sizes, int n_in,
                              void* d_out, int out_size)
{
    const float* z       = (const float*)d_in[0];
    const int*   n_nodes = (const int*)  d_in[1];
    /* d_in[2] = n_edges (unused) */
    const float* gu      = (const float*)d_in[3];
    const float* emb     = (const float*)d_in[4];
    const float* pe      = (const float*)d_in[5];
    const float* W_pre   = (const float*)d_in[6];
    const float* b_pre   = (const float*)d_in[7];
    const float* Wih0    = (const float*)d_in[8];
    const float* Whh0    = (const float*)d_in[9];
    const float* bih0    = (const float*)d_in[10];
    const float* bhh0    = (const float*)d_in[11];
    const float* Wih1    = (const float*)d_in[12];
    const float* Whh1    = (const float*)d_in[13];
    const float* bih1    = (const float*)d_in[14];
    const float* bhh1    = (const float*)d_in[15];
    /* node_W */
    const float* node_W  = (const float*)d_in[16];
    const float* adj_W1  = (const float*)d_in[17];
    const float* adj_b1  = (const float*)d_in[18];
    const float* adj_W2  = (const float*)d_in[19];
    const float* adj_b2  = (const float*)d_in[20];
    float* out = (float*)d_out;

    // Resolve device-global scratch addresses
    float *Cm, *zWT, *AT, *D, *P, *Q, *gh, *h1T, *h2T, *gi1, *U, *V;
    cudaGetSymbolAddress((void**)&Cm,  g_Cm);
    cudaGetSymbolAddress((void**)&zWT, g_zWT);
    cudaGetSymbolAddress((void**)&AT,  g_AT);
    cudaGetSymbolAddress((void**)&D,   g_D);
    cudaGetSymbolAddress((void**)&P,   g_P);
    cudaGetSymbolAddress((void**)&Q,   g_Q);
    cudaGetSymbolAddress((void**)&gh,  g_gh);
    cudaGetSymbolAddress((void**)&h1T, g_h1T);
    cudaGetSymbolAddress((void**)&h2T, g_h2T);
    cudaGetSymbolAddress((void**)&gi1, g_gi1);
    cudaGetSymbolAddress((void**)&U,   g_U);
    cudaGetSymbolAddress((void**)&V,   g_V);

    // --- precompute -------------------------------------------------------
    pairidx_k<<<8, 256>>>();
    precompC_k<<<MNODES, 256>>>(pe, emb, W_pre, b_pre);
    precompzW_k<<<BATCH, 256>>>(z, W_pre);

    // AT[g][b] = zW @ Wih0.T, transposed:  M=1536(g), N=128(b), K=256
    sgemm_k<64, 32, 16, 4, 2, true, false><<<dim3(BATCH / 32, G3 / 64), 256>>>(
        Wih0, zWT, AT, nullptr, LATENT, LATENT, BATCH, BATCH, 0, 0, 0);

    // D[t][g] = Cm @ Wih0.T : M=64, N=1536, K=256
    sgemm_k<64, 64, 16, 4, 4, true, true><<<dim3(G3 / 64, 1), 256>>>(
        Cm, Wih0, D, nullptr, LATENT, LATENT, LATENT, G3, 0, 0, 0);

    // P = adj_W1[:, :512] @ node_W  and  Q = adj_W1[:, 512:] @ node_W  (512x512, K=512)
    sgemm_k<64, 64, 16, 4, 4, true, false><<<dim3(8, 8), 256>>>(
        adj_W1, node_W, P, nullptr, HIDDEN, 2 * HIDDEN, HIDDEN, HIDDEN, 0, 0, 0);
    sgemm_k<64, 64, 16, 4, 4, true, false><<<dim3(8, 8), 256>>>(
        adj_W1 + HIDDEN, node_W, Q, nullptr, HIDDEN, 2 * HIDDEN, HIDDEN, HIDDEN, 0, 0, 0);

    // --- GRU layer 0 (sequential) ----------------------------------------
    for (int t = 0; t < MNODES; t++) {
        if (t > 0) {
            // gh[g][b] = Whh0 @ h_prev : M=1536, N=128, K=512
            sgemm_k<64, 32, 16, 4, 2, true, false><<<dim3(BATCH / 32, G3 / 64), 256>>>(
                Whh0, h1T + (long)(t - 1) * HIDDEN * BATCH, gh, nullptr,
                HIDDEN, HIDDEN, BATCH, BATCH, 0, 0, 0);
        }
        gate0_k<<<256, 256>>>(bih0, bhh0, n_nodes, t, t == 0);
    }

    // gi1[t][g][b] = Wih1 @ h1[t] : batched over t (z=64)
    sgemm_k<64, 64, 16, 4, 4, true, false><<<dim3(BATCH / 64, G3 / 64, MNODES), 256>>>(
        Wih1, h1T, gi1, nullptr, HIDDEN, HIDDEN, BATCH, BATCH,
        0, (long)HIDDEN * BATCH, (long)G3 * BATCH);

    // --- GRU layer 1 (sequential) ----------------------------------------
    for (int t = 0; t < MNODES; t++) {
        if (t > 0) {
            sgemm_k<64, 32, 16, 4, 2, true, false><<<dim3(BATCH / 32, G3 / 64), 256>>>(
                Whh1, h2T + (long)(t - 1) * HIDDEN * BATCH, gh, nullptr,
                HIDDEN, HIDDEN, BATCH, BATCH, 0, 0, 0);
        }
        gate1_k<<<256, 256>>>(bih1, bhh1, t, t == 0);
    }

    // --- U / V : batched over t, A is K-major (h2T[t] is [k][b]) ----------
    // U[b][t][h] = h2[t] @ P.T : M=128(b), N=512(h), K=512
    sgemm_k<64, 64, 16, 4, 4, false, true><<<dim3(HIDDEN / 64, BATCH / 64, MNODES), 256>>>(
        h2T, P, U, nullptr, HIDDEN, BATCH, HIDDEN, MNODES * HIDDEN,
        (long)HIDDEN * BATCH, 0, (long)HIDDEN);
    sgemm_k<64, 64, 16, 4, 4, false, true><<<dim3(HIDDEN / 64, BATCH / 64, MNODES), 256>>>(
        h2T, Q, V, adj_b1, HIDDEN, BATCH, HIDDEN, MNODES * HIDDEN,
        (long)HIDDEN * BATCH, 0, (long)HIDDEN);

    // --- output -----------------------------------------------------------
    zero_k<<<(BATCH * MNODES * MNODES + 255) / 256, 256>>>(out, BATCH * MNODES * MNODES);
    pair_k<<<dim3(BATCH, 2), 256>>>(adj_W2, adj_b2, gu, n_nodes, out);
}

// round 4
// speedup vs baseline: 1.0006x; 1.0006x over previous
#include <cuda_runtime.h>
#include <math.h>

// ---------------------------------------------------------------------------
// Problem constants
// ---------------------------------------------------------------------------
#define BATCH    128
#define LATENT   256
#define HIDDEN   512
#define MNODES   64
#define NPAIRS   2016           // 64*63/2
#define G3       (3*HIDDEN)     // 1536

// ---------------------------------------------------------------------------
// Device scratch (no cudaMalloc allowed)
// ---------------------------------------------------------------------------
__device__ float g_Cm  [MNODES * LATENT];          // C[t][l]
__device__ float g_zWT [LATENT * BATCH];           // zW^T [l][b]
__device__ float g_AT  [G3 * BATCH];               // A^T  [g][b]
__device__ float g_D   [MNODES * G3];              // D    [t][g]
__device__ float g_P   [HIDDEN * HIDDEN];          // adj_W1a @ node_W
__device__ float g_Q   [HIDDEN * HIDDEN];          // adj_W1b @ node_W
__device__ float g_gh  [G3 * BATCH];               // recurrent GEMM out [g][b]
__device__ float g_h1T [MNODES * HIDDEN * BATCH];  // layer-0 hidden [t][k][b]
__device__ float g_h2T [MNODES * HIDDEN * BATCH];  // layer-1 hidden [t][k][b]
__device__ float g_gi1 [MNODES * G3 * BATCH];      // layer-1 input proj [t][g][b]
__device__ float g_U   [BATCH * MNODES * HIDDEN];  // [b][t][h]
__device__ float g_V   [BATCH * MNODES * HIDDEN];  // [b][t][h] (+adj_b1)
__device__ int   g_ii  [NPAIRS];
__device__ int   g_jj  [NPAIRS];

// ---------------------------------------------------------------------------
// Generic tiled fp32 GEMM:  C[m][n] = sum_k A(m,k) * B(n,k)  (+ bias[n])
//  A_ROW : A stored row-major (M x K, lda) else K-major (K x M, lda)
//  B_NK  : B stored (N x K, ldb) else (K x N, ldb)
//  C row-major with ldc. blockIdx.z batching via aZ/bZ/cZ element strides.
// ---------------------------------------------------------------------------
template<int BM, int BN, int BK, int TM, int TN, bool A_ROW, bool B_NK>
__global__ void sgemm_k(const float* __restrict__ Ag, const float* __restrict__ Bg,
                        float* __restrict__ Cg, const float* __restrict__ bias,
                        int K, int lda, int ldb, int ldc,
                        long aZ, long bZ, long cZ)
{
    const float* A = Ag + (long)blockIdx.z * aZ;
    const float* B = Bg + (long)blockIdx.z * bZ;
    float*       C = Cg + (long)blockIdx.z * cZ;

    __shared__ float As[BK][BM];
    __shared__ float Bs[BK][BN];

    constexpr int NTH = (BM / TM) * (BN / TN);
    const int tid  = threadIdx.x;
    const int tcol = tid % (BN / TN);
    const int trow = tid / (BN / TN);
    const int m0   = blockIdx.y * BM;
    const int n0   = blockIdx.x * BN;

    float acc[TM][TN];
#pragma unroll
    for (int i = 0; i < TM; i++)
#pragma unroll
        for (int j = 0; j < TN; j++) acc[i][j] = 0.f;

    for (int k0 = 0; k0 < K; k0 += BK) {
#pragma unroll
        for (int idx = tid; idx < BM * BK; idx += NTH) {
            int m = idx / BK, kk = idx % BK;
            As[kk][m] = A_ROW ? A[(long)(m0 + m) * lda + (k0 + kk)]
                              : A[(long)(k0 + kk) * lda + (m0 + m)];
        }
#pragma unroll
        for (int idx = tid; idx < BK * BN; idx += NTH) {
            int kk = idx / BN, n = idx % BN;
            Bs[kk][n] = B_NK ? B[(long)(n0 + n) * ldb + (k0 + kk)]
                             : B[(long)(k0 + kk) * ldb + (n0 + n)];
        }
        __syncthreads();
#pragma unroll
        for (int kk = 0; kk < BK; kk++) {
            float a[TM], b[TN];
#pragma unroll
            for (int i = 0; i < TM; i++) a[i] = As[kk][trow * TM + i];
#pragma unroll
            for (int j = 0; j < TN; j++) b[j] = Bs[kk][tcol * TN + j];
#pragma unroll
            for (int i = 0; i < TM; i++)
#pragma unroll
                for (int j = 0; j < TN; j++)
                    acc[i][j] = fmaf(a[i], b[j], acc[i][j]);
        }
        __syncthreads();
    }

#pragma unroll
    for (int i = 0; i < TM; i++) {
        int m = m0 + trow * TM + i;
#pragma unroll
        for (int j = 0; j < TN; j++) {
            int n = n0 + tcol * TN + j;
            float v = acc[i][j];
            if (bias) v += bias[n];
            C[(long)m * ldc + n] = v;
        }
    }
}

// ---------------------------------------------------------------------------
// Small precompute kernels
// ---------------------------------------------------------------------------
__global__ void precompC_k(const float* __restrict__ pe, const float* __restrict__ emb,
                           const float* __restrict__ W_pre, const float* __restrict__ b_pre)
{
    int t = blockIdx.x, l = threadIdx.x;
    const float* w = W_pre + l * 512;
    float acc = b_pre[l];
    for (int d = 0; d < 256; d++)
        acc += pe[t * 256 + d] * w[d] + emb[t * 256 + d] * w[256 + d];
    g_Cm[t * 256 + l] = acc;
}

__global__ void precompzW_k(const float* __restrict__ z, const float* __restrict__ W_pre)
{
    int b = blockIdx.x, l = threadIdx.x;
    const float* w = W_pre + l * 512;
    float acc = 0.f;
    for (int d = 0; d < 256; d++)
        acc += z[b * 256 + d] * w[d];
    g_zWT[l * BATCH + b] = acc;
}

__global__ void pairidx_k()
{
    int p = blockIdx.x * blockDim.x + threadIdx.x;
    if (p >= NPAIRS) return;
    int i = 0, rem = p;
    while (rem >= 63 - i) { rem -= 63 - i; i++; }
    g_ii[p] = i;
    g_jj[p] = i + 1 + rem;
}

__global__ void zero_k(float* p, int n)
{
    int i = blockIdx.x * blockDim.x + threadIdx.x;
    if (i < n) p[i] = 0.f;
}

// ---------------------------------------------------------------------------
// GRU gate kernels. gh (no bias) laid out [g][b]; hidden seq [t][k][b].
// ---------------------------------------------------------------------------
__device__ __forceinline__ float sigm(float x) { return 1.f / (1.f + expf(-x)); }

__global__ void gate0_k(const float* __restrict__ bih, const float* __restrict__ bhh,
                        const int* __restrict__ n_nodes, int t, int first)
{
    int idx = blockIdx.x * blockDim.x + threadIdx.x;   // 65536
    int b = idx & (BATCH - 1);
    int j = idx >> 7;

    float ghr = 0.f, ghz = 0.f, ghn = 0.f, hprev = 0.f;
    if (!first) {
        ghr = g_gh[j * BATCH + b];
        ghz = g_gh[(HIDDEN + j) * BATCH + b];
        ghn = g_gh[(2 * HIDDEN + j) * BATCH + b];
        hprev = g_h1T[((long)(t - 1) * HIDDEN + j) * BATCH + b];
    }
    float gir = bih[j], giz = bih[HIDDEN + j], gin = bih[2 * HIDDEN + j];
    if (t < n_nodes[b]) {
        gir += g_AT[j * BATCH + b]                + g_D[t * G3 + j];
        giz += g_AT[(HIDDEN + j) * BATCH + b]     + g_D[t * G3 + HIDDEN + j];
        gin += g_AT[(2 * HIDDEN + j) * BATCH + b] + g_D[t * G3 + 2 * HIDDEN + j];
    }
    ghr += bhh[j]; ghz += bhh[HIDDEN + j]; ghn += bhh[2 * HIDDEN + j];

    float r  = sigm(gir + ghr);
    float zg = sigm(giz + ghz);
    float n  = tanhf(gin + r * ghn);
    float h  = (1.f - zg) * n + zg * hprev;
    g_h1T[((long)t * HIDDEN + j) * BATCH + b] = h;
}

__global__ void gate1_k(const float* __restrict__ bih, const float* __restrict__ bhh,
                        int t, int first)
{
    int idx = blockIdx.x * blockDim.x + threadIdx.x;
    int b = idx & (BATCH - 1);
    int j = idx >> 7;

    float ghr = 0.f, ghz = 0.f, ghn = 0.f, hprev = 0.f;
    if (!first) {
        ghr = g_gh[j * BATCH + b];
        ghz = g_gh[(HIDDEN + j) * BATCH + b];
        ghn = g_gh[(2 * HIDDEN + j) * BATCH + b];
        hprev = g_h2T[((long)(t - 1) * HIDDEN + j) * BATCH + b];
    }
    const float* gi = g_gi1 + (long)t * G3 * BATCH;
    float gir = gi[j * BATCH + b]                + bih[j];
    float giz = gi[(HIDDEN + j) * BATCH + b]     + bih[HIDDEN + j];
    float gin = gi[(2 * HIDDEN + j) * BATCH + b] + bih[2 * HIDDEN + j];
    ghr += bhh[j]; ghz += bhh[HIDDEN + j]; ghn += bhh[2 * HIDDEN + j];

    float r  = sigm(gir + ghr);
    float zg = sigm(giz + ghz);
    float n  = tanhf(gin + r * ghn);
    float h  = (1.f - zg) * n + zg * hprev;
    g_h2T[((long)t * HIDDEN + j) * BATCH + b] = h;
}

// ---------------------------------------------------------------------------
// Pair kernel: logits + Gumbel hard decision -> writes 1s into zeroed adj.
//   hmid = relu(U[b,i] + V[b,j])   (V already has adj_b1 folded in)
//   l0 = hmid . W2[0] + b2[0] ; l1 = hmid . W2[1] + b2[1]
//   adj[b,i,j] = adj[b,j,i] = (l0+g0 >= l1+g1)
// grid (128, 2), 256 threads (8 warps): warp per pair, strided.
// ---------------------------------------------------------------------------
__global__ void pair_k(const float* __restrict__ W2, const float* __restrict__ b2,
                       const float* __restrict__ gu, const int* __restrict__ n_nodes,
                       float* __restrict__ out)
{
    int b    = blockIdx.x;
    int warp = (int)(blockIdx.y * 8 + (threadIdx.x >> 5));
    int lane = threadIdx.x & 31;
    int nb   = n_nodes[b];
    float* ob = out + (long)b * (MNODES * MNODES);

    float4 w2a[4], w2b[4];
#pragma unroll
    for (int q = 0; q < 4; q++) {
        w2a[q] = *(const float4*)(W2 + 4 * lane + 128 * q);
        w2b[q] = *(const float4*)(W2 + HIDDEN + 4 * lane + 128 * q);
    }

    for (int p = warp; p < NPAIRS; p += 16) {
        int j = g_jj[p];
        if (j >= nb) continue;           // i<j, so j<nb implies i<nb
        int i = g_ii[p];
        const float* Ui = g_U + ((long)b * MNODES + i) * HIDDEN;
        const float* Vj = g_V + ((long)b * MNODES + j) * HIDDEN;
        float a0 = 0.f, a1 = 0.f;
#pragma unroll
        for (int q = 0; q < 4; q++) {
            float4 u = *(const float4*)(Ui + 4 * lane + 128 * q);
            float4 v = *(const float4*)(Vj + 4 * lane + 128 * q);
            float m;
            m = fmaxf(u.x + v.x, 0.f); a0 = fmaf(m, w2a[q].x, a0); a1 = fmaf(m, w2b[q].x, a1);
            m = fmaxf(u.y + v.y, 0.f); a0 = fmaf(m, w2a[q].y, a0); a1 = fmaf(m, w2b[q].y, a1);
            m = fmaxf(u.z + v.z, 0.f); a0 = fmaf(m, w2a[q].z, a0); a1 = fmaf(m, w2b[q].z, a1);
            m = fmaxf(u.w + v.w, 0.f); a0 = fmaf(m, w2a[q].w, a0); a1 = fmaf(m, w2b[q].w, a1);
        }
#pragma unroll
        for (int s = 16; s > 0; s >>= 1) {
            a0 += __shfl_xor_sync(0xffffffffu, a0, s);
            a1 += __shfl_xor_sync(0xffffffffu, a1, s);
        }
        if (lane == 0) {
            float l0 = a0 + b2[0];
            float l1 = a1 + b2[1];
            const float* g = gu + ((long)b * NPAIRS + p) * 2;
            float g0 = -logf(-logf(g[0] + 1e-10f) + 1e-10f);
            float g1 = -logf(-logf(g[1] + 1e-10f) + 1e-10f);
            if (l0 + g0 >= l1 + g1) {
                ob[i * MNODES + j] = 1.f;
                ob[j * MNODES + i] = 1.f;
            }
        }
    }
}

// ---------------------------------------------------------------------------
// Host launch sequence (graph-capturable: kernel launches only)
// ---------------------------------------------------------------------------
extern "C" void kernel_launch(void* const* d_in, const int* in_sizes, int n_in,
                              void* d_out, int out_size)
{
    const float* z       = (const float*)d_in[0];
    const int*   n_nodes = (const int*)  d_in[1];
    /* d_in[2] = n_edges (unused) */
    const float* gu      = (const float*)d_in[3];
    const float* emb     = (const float*)d_in[4];
    const float* pe      = (const float*)d_in[5];
    const float* W_pre   = (const float*)d_in[6];
    const float* b_pre   = (const float*)d_in[7];
    const float* Wih0    = (const float*)d_in[8];
    const float* Whh0    = (const float*)d_in[9];
    const float* bih0    = (const float*)d_in[10];
    const float* bhh0    = (const float*)d_in[11];
    const float* Wih1    = (const float*)d_in[12];
    const float* Whh1    = (const float*)d_in[13];
    const float* bih1    = (const float*)d_in[14];
    const float* bhh1    = (const float*)d_in[15];
    /* node_W */
    const float* node_W  = (const float*)d_in[16];
    const float* adj_W1  = (const float*)d_in[17];
    const float* adj_b1  = (const float*)d_in[18];
    const float* adj_W2  = (const float*)d_in[19];
    const float* adj_b2  = (const float*)d_in[20];
    float* out = (float*)d_out;

    // Resolve device-global scratch addresses
    float *Cm, *zWT, *AT, *D, *P, *Q, *gh, *h1T, *h2T, *gi1, *U, *V;
    cudaGetSymbolAddress((void**)&Cm,  g_Cm);
    cudaGetSymbolAddress((void**)&zWT, g_zWT);
    cudaGetSymbolAddress((void**)&AT,  g_AT);
    cudaGetSymbolAddress((void**)&D,   g_D);
    cudaGetSymbolAddress((void**)&P,   g_P);
    cudaGetSymbolAddress((void**)&Q,   g_Q);
    cudaGetSymbolAddress((void**)&gh,  g_gh);
    cudaGetSymbolAddress((void**)&h1T, g_h1T);
    cudaGetSymbolAddress((void**)&h2T, g_h2T);
    cudaGetSymbolAddress((void**)&gi1, g_gi1);
    cudaGetSymbolAddress((void**)&U,   g_U);
    cudaGetSymbolAddress((void**)&V,   g_V);

    // --- precompute -------------------------------------------------------
    pairidx_k<<<8, 256>>>();
    precompC_k<<<MNODES, 256>>>(pe, emb, W_pre, b_pre);
    precompzW_k<<<BATCH, 256>>>(z, W_pre);

    // AT[g][b] = zW @ Wih0.T, transposed:  M=1536(g), N=128(b), K=256
    sgemm_k<64, 32, 16, 4, 2, true, false><<<dim3(BATCH / 32, G3 / 64), 256>>>(
        Wih0, zWT, AT, nullptr, LATENT, LATENT, BATCH, BATCH, 0, 0, 0);

    // D[t][g] = Cm @ Wih0.T : M=64, N=1536, K=256
    sgemm_k<64, 64, 16, 4, 4, true, true><<<dim3(G3 / 64, 1), 256>>>(
        Cm, Wih0, D, nullptr, LATENT, LATENT, LATENT, G3, 0, 0, 0);

    // P = adj_W1[:, :512] @ node_W  and  Q = adj_W1[:, 512:] @ node_W  (512x512, K=512)
    sgemm_k<64, 64, 16, 4, 4, true, false><<<dim3(8, 8), 256>>>(
        adj_W1, node_W, P, nullptr, HIDDEN, 2 * HIDDEN, HIDDEN, HIDDEN, 0, 0, 0);
    sgemm_k<64, 64, 16, 4, 4, true, false><<<dim3(8, 8), 256>>>(
        adj_W1 + HIDDEN, node_W, Q, nullptr, HIDDEN, 2 * HIDDEN, HIDDEN, HIDDEN, 0, 0, 0);

    // --- GRU layer 0 (sequential) ----------------------------------------
    for (int t = 0; t < MNODES; t++) {
        if (t > 0) {
            // gh[g][b] = Whh0 @ h_prev : M=1536, N=128, K=512
            sgemm_k<64, 32, 16, 4, 2, true, false><<<dim3(BATCH / 32, G3 / 64), 256>>>(
                Whh0, h1T + (long)(t - 1) * HIDDEN * BATCH, gh, nullptr,
                HIDDEN, HIDDEN, BATCH, BATCH, 0, 0, 0);
        }
        gate0_k<<<256, 256>>>(bih0, bhh0, n_nodes, t, t == 0);
    }

    // gi1[t][g][b] = Wih1 @ h1[t] : batched over t (z=64)
    sgemm_k<64, 64, 16, 4, 4, true, false><<<dim3(BATCH / 64, G3 / 64, MNODES), 256>>>(
        Wih1, h1T, gi1, nullptr, HIDDEN, HIDDEN, BATCH, BATCH,
        0, (long)HIDDEN * BATCH, (long)G3 * BATCH);

    // --- GRU layer 1 (sequential) ----------------------------------------
    for (int t = 0; t < MNODES; t++) {
        if (t > 0) {
            sgemm_k<64, 32, 16, 4, 2, true, false><<<dim3(BATCH / 32, G3 / 64), 256>>>(
                Whh1, h2T + (long)(t - 1) * HIDDEN * BATCH, gh, nullptr,
                HIDDEN, HIDDEN, BATCH, BATCH, 0, 0, 0);
        }
        gate1_k<<<256, 256>>>(bih1, bhh1, t, t == 0);
    }

    // --- U / V : batched over t, A is K-major (h2T[t] is [k][b]) ----------
    // U[b][t][h] = h2[t] @ P.T : M=128(b), N=512(h), K=512
    sgemm_k<64, 64, 16, 4, 4, false, true><<<dim3(HIDDEN / 64, BATCH / 64, MNODES), 256>>>(
        h2T, P, U, nullptr, HIDDEN, BATCH, HIDDEN, MNODES * HIDDEN,
        (long)HIDDEN * BATCH, 0, (long)HIDDEN);
    sgemm_k<64, 64, 16, 4, 4, false, true><<<dim3(HIDDEN / 64, BATCH / 64, MNODES), 256>>>(
        h2T, Q, V, adj_b1, HIDDEN, BATCH, HIDDEN, MNODES * HIDDEN,
        (long)HIDDEN * BATCH, 0, (long)HIDDEN);

    // --- output -----------------------------------------------------------
    zero_k<<<(BATCH * MNODES * MNODES + 255) / 256, 256>>>(out, BATCH * MNODES * MNODES);
    pair_k<<<dim3(BATCH, 2), 256>>>(adj_W2, adj_b2, gu, n_nodes, out);
}